// round 14
// baseline (speedup 1.0000x reference)
#include <cuda_runtime.h>
#include <cuda_fp16.h>
#include <cstdint>

// Problem constants
#define B_     256
#define C_IN_  8
#define N_     4096
#define K_     9
#define S_     2
#define C_OUT_ 8

#define W_ELEMS (S_ * C_IN_ * K_ * C_OUT_)   // 1152 floats

// Main tiling: block = 16 n x 64 b, 8 warps. Warp-item = (n, 16-b tile).
#define NT  16
#define BT  64

// Scratch: x as fp16 in (n, b, c) layout — c innermost (8 halves = 16B per (n,b)).
// One n-plane = B_*C_IN_*2 = 4096 bytes (power of 2 -> shift addressing).
__device__ __half g_xh[N_ * B_ * C_IN_];   // 16.8 MB

// ---------------------------------------------------------------------------
// K1: x (B, C_IN, N) f32 -> g_xh (N, B, C_IN) fp16.
// Block: 32 n x 32 b x 8 c. grid (N/32, B/32) = 1024 blocks.
// ---------------------------------------------------------------------------
__global__ __launch_bounds__(256) void transpose_x_kernel(const float* __restrict__ x)
{
    __shared__ float tf[256 * 33];   // 33.8 KB
    const int tid = threadIdx.x;
    const int l   = tid & 31;
    const int w   = tid >> 5;
    const int n0  = blockIdx.x * 32;
    const int b0  = blockIdx.y * 32;

    // Phase 1: 256 (b,c) rows; warp w handles rows w*32 .. w*32+31. Lanes on n.
    #pragma unroll
    for (int r = 0; r < 32; ++r) {
        const int row = w * 32 + r;          // bc index
        const int b = row >> 3;
        const int c = row & 7;
        const float v = x[((size_t)(b0 + b) * C_IN_ + c) * N_ + n0 + l];
        tf[(c * 32 + b) * 33 + l] = v;
    }
    __syncthreads();

    // Phase 2: per iteration warp w handles n = w + 8i, lanes = b.
    // Banks (33*(32c+b) + n) mod 32 = (b + n) mod 32: lanes=b -> conflict-free.
    #pragma unroll
    for (int i = 0; i < 4; ++i) {
        const int n = w + 8 * i;
        __half2 h01 = __floats2half2_rn(tf[(0 * 32 + l) * 33 + n],
                                        tf[(1 * 32 + l) * 33 + n]);
        __half2 h23 = __floats2half2_rn(tf[(2 * 32 + l) * 33 + n],
                                        tf[(3 * 32 + l) * 33 + n]);
        __half2 h45 = __floats2half2_rn(tf[(4 * 32 + l) * 33 + n],
                                        tf[(5 * 32 + l) * 33 + n]);
        __half2 h67 = __floats2half2_rn(tf[(6 * 32 + l) * 33 + n],
                                        tf[(7 * 32 + l) * 33 + n]);
        uint4 val;
        val.x = *reinterpret_cast<uint32_t*>(&h01);
        val.y = *reinterpret_cast<uint32_t*>(&h23);
        val.z = *reinterpret_cast<uint32_t*>(&h45);
        val.w = *reinterpret_cast<uint32_t*>(&h67);
        *reinterpret_cast<uint4*>(
            &g_xh[((size_t)(n0 + n) * B_ + b0 + l) * C_IN_]) = val;
    }
}

// ---------------------------------------------------------------------------
// K2: tensor-core main kernel (R13 body + 32-bit shift addressing + no pad loads).
// Per item (n, 16-b tile): D(16b x 8d) = A(16b x 80ck) x B(80ck x 8d) via
// 5x mma.sync.m16n8k16 (fp16 in, f32 accum), K ordered col = k*8 + c.
// A fragments loaded straight from g_xh: each frag reg = one 128B line.
// Gather address = base + (nbr<<12) + rowoff  (all 32-bit; nbr pre-shifted
// in smem). q=4 second-row loads skipped (B-half is zero).
// grid (N/16, B/64) = 1024 blocks, 4 CTAs/SM.
// ---------------------------------------------------------------------------
#define SIDX(d, r, nl) ((d) * 1092 + (r) * 17 + (nl))

__global__ __launch_bounds__(256, 4)
void lattice_main_kernel(const int*   __restrict__ nbr,
                         const int*   __restrict__ sub_ids,
                         const float* __restrict__ weight,
                         const float* __restrict__ bias,
                         float*       __restrict__ out)
{
    __shared__ float sw[W_ELEMS];        // 4.6 KB
    __shared__ float sout[8 * 1092];     // 34.9 KB
    __shared__ int   snbr[NT][9];        // pre-shifted: nbr << 12
    __shared__ int   ssub[NT];
    __shared__ float sbias[S_ * C_OUT_];

    const int tid = threadIdx.x;
    const int l   = tid & 31;
    const int w   = tid >> 5;
    const int g   = l >> 2;     // groupID (fragment row / d for B)
    const int t   = l & 3;      // thread-in-group

    const int n0 = blockIdx.x * NT;
    const int b0 = blockIdx.y * BT;

    // Prologue: weights + metadata to smem.
    #pragma unroll
    for (int i = tid; i < W_ELEMS; i += 256) sw[i] = weight[i];
    if (tid < NT * 9) {
        const int nl = tid / 9, kk = tid % 9;
        snbr[nl][kk] = nbr[(n0 + nl) * K_ + kk] << 12;   // byte offset of n-plane
    } else if (tid < NT * 9 + NT) {
        ssub[tid - NT * 9] = sub_ids[n0 + (tid - NT * 9)];
    } else if (tid < NT * 9 + NT + S_ * C_OUT_) {
        sbias[tid - NT * 9 - NT] = bias[tid - NT * 9 - NT];
    }
    __syncthreads();

    // Build B fragments (fp16) for both s, all 5 K-chunks.
    // bf0 = {W[s][2t][2q][g], W[s][2t+1][2q][g]}, bf1 same with k=2q+1 (q=4: zero).
    uint32_t bf0[S_][5], bf1[S_][5];
    #pragma unroll
    for (int s = 0; s < S_; ++s) {
        #pragma unroll
        for (int q = 0; q < 5; ++q) {
            const int base0 = ((s * C_IN_ + 2 * t)     * K_ + 2 * q) * C_OUT_ + g;
            const int base1 = ((s * C_IN_ + 2 * t + 1) * K_ + 2 * q) * C_OUT_ + g;
            __half2 h0 = __floats2half2_rn(sw[base0], sw[base1]);
            bf0[s][q] = *reinterpret_cast<uint32_t*>(&h0);
            if (q < 4) {
                __half2 h1 = __floats2half2_rn(sw[base0 + C_OUT_], sw[base1 + C_OUT_]);
                bf1[s][q] = *reinterpret_cast<uint32_t*>(&h1);
            } else {
                bf1[s][q] = 0u;
            }
        }
    }

    const char* xbase = reinterpret_cast<const char*>(g_xh);

    // Main: 8 items per warp. item = w*8 + it -> nl = item>>2, bt = item&3.
    #pragma unroll 1
    for (int it = 0; it < 8; ++it) {
        const int item = w * 8 + it;
        const int nl = item >> 2;
        const int bt = item & 3;
        const int s  = ssub[nl];                 // warp-uniform
        const int* nbrn = snbr[nl];

        float c0 = sbias[s * C_OUT_ + 2 * t];
        float c1 = sbias[s * C_OUT_ + 2 * t + 1];
        float c2 = c0, c3 = c1;

        // byte offset within an n-plane: ((b0 + bt*16 + g)*8 + 2t)*2 < 4096
        const uint32_t rowoff = (uint32_t)((b0 + bt * 16 + g) * 16 + 4 * t);

        #pragma unroll
        for (int q = 0; q < 5; ++q) {
            const uint32_t o0 = (uint32_t)nbrn[2 * q] + rowoff;
            const uint32_t a0 = __ldg(reinterpret_cast<const uint32_t*>(xbase + o0));
            const uint32_t a1 = __ldg(reinterpret_cast<const uint32_t*>(xbase + o0 + 128));
            uint32_t a2 = 0u, a3 = 0u;
            if (q < 4) {   // q=4: second B-half is zero -> rows dead, skip loads
                const uint32_t o1 = (uint32_t)nbrn[2 * q + 1] + rowoff;
                a2 = __ldg(reinterpret_cast<const uint32_t*>(xbase + o1));
                a3 = __ldg(reinterpret_cast<const uint32_t*>(xbase + o1 + 128));
            }
            const uint32_t B0 = s ? bf0[1][q] : bf0[0][q];
            const uint32_t B1 = s ? bf1[1][q] : bf1[0][q];
            asm volatile(
                "mma.sync.aligned.m16n8k16.row.col.f32.f16.f16.f32 "
                "{%0,%1,%2,%3}, {%4,%5,%6,%7}, {%8,%9}, {%0,%1,%2,%3};"
                : "+f"(c0), "+f"(c1), "+f"(c2), "+f"(c3)
                : "r"(a0), "r"(a1), "r"(a2), "r"(a3), "r"(B0), "r"(B1));
        }

        // Stage D: rows r=bt*16+g (c0,c1) and r+8 (c2,c3); cols d=2t, 2t+1.
        // Banks (4d + 17r + nl): bijective over the warp -> conflict-free.
        const int r = bt * 16 + g;
        sout[SIDX(2 * t,     r,     nl)] = c0;
        sout[SIDX(2 * t + 1, r,     nl)] = c1;
        sout[SIDX(2 * t,     r + 8, nl)] = c2;
        sout[SIDX(2 * t + 1, r + 8, nl)] = c3;
    }
    __syncthreads();

    // Epilogue: 512 (b,d) rows x 16 n. Warp w owns rows [w*64, w*64+64);
    // half-warps cover row pairs; 16 lanes = 16 consecutive n (64B line).
    {
        const int h  = l >> 4;
        const int nl = l & 15;
        #pragma unroll
        for (int p = 0; p < 32; ++p) {
            const int r512 = w * 64 + 2 * p + h;   // = b*8 + d
            const int b = r512 >> 3;
            const int d = r512 & 7;
            const float v = sout[SIDX(d, b, nl)];
            out[((size_t)(b0 + b) * C_OUT_ + d) * N_ + n0 + nl] = v;
        }
    }
}

extern "C" void kernel_launch(void* const* d_in, const int* in_sizes, int n_in,
                              void* d_out, int out_size)
{
    const float* x       = (const float*)d_in[0];   // (B, C_IN, N) f32
    const int*   nbr     = (const int*)  d_in[1];   // (N, K) i32
    const int*   sub_ids = (const int*)  d_in[2];   // (N,) i32
    const float* weight  = (const float*)d_in[3];   // (S, C_IN, K, C_OUT) f32
    const float* bias    = (const float*)d_in[4];   // (S, C_OUT) f32
    float*       out     = (float*)d_out;           // (B, C_OUT, N) f32

    dim3 tgrid(N_ / 32, B_ / 32);
    transpose_x_kernel<<<tgrid, 256>>>(x);

    dim3 mgrid(N_ / NT, B_ / BT);
    lattice_main_kernel<<<mgrid, 256>>>(nbr, sub_ids, weight, bias, out);
}

// round 15
// speedup vs baseline: 1.0419x; 1.0419x over previous
#include <cuda_runtime.h>
#include <cuda_fp16.h>
#include <cstdint>

// Problem constants
#define B_     256
#define C_IN_  8
#define N_     4096
#define K_     9
#define S_     2
#define C_OUT_ 8

#define W_ELEMS (S_ * C_IN_ * K_ * C_OUT_)   // 1152 floats

// Main tiling: block = 16 n x 64 b, 8 warps. Warp-item = (n, 16-b tile).
#define NT  16
#define BT  64

// Scratch: x as fp16 in (n, b, c) layout — c innermost (8 halves = 16B per (n,b)).
// One n-plane = B_*C_IN_*2 = 4096 bytes (power of 2 -> shift addressing).
__device__ __half g_xh[N_ * B_ * C_IN_];   // 16.8 MB

// ---------------------------------------------------------------------------
// K1: x (B, C_IN, N) f32 -> g_xh (N, B, C_IN) fp16.
// Block: 32 n x 32 b x 8 c. grid (N/32, B/32) = 1024 blocks.
// ---------------------------------------------------------------------------
__global__ __launch_bounds__(256) void transpose_x_kernel(const float* __restrict__ x)
{
    __shared__ float tf[256 * 33];   // 33.8 KB
    const int tid = threadIdx.x;
    const int l   = tid & 31;
    const int w   = tid >> 5;
    const int n0  = blockIdx.x * 32;
    const int b0  = blockIdx.y * 32;

    // Phase 1: 256 (b,c) rows; warp w handles rows w*32 .. w*32+31. Lanes on n.
    #pragma unroll
    for (int r = 0; r < 32; ++r) {
        const int row = w * 32 + r;          // bc index
        const int b = row >> 3;
        const int c = row & 7;
        const float v = x[((size_t)(b0 + b) * C_IN_ + c) * N_ + n0 + l];
        tf[(c * 32 + b) * 33 + l] = v;
    }
    __syncthreads();

    // Phase 2: per iteration warp w handles n = w + 8i, lanes = b.
    // Banks (33*(32c+b) + n) mod 32 = (b + n) mod 32: lanes=b -> conflict-free.
    #pragma unroll
    for (int i = 0; i < 4; ++i) {
        const int n = w + 8 * i;
        __half2 h01 = __floats2half2_rn(tf[(0 * 32 + l) * 33 + n],
                                        tf[(1 * 32 + l) * 33 + n]);
        __half2 h23 = __floats2half2_rn(tf[(2 * 32 + l) * 33 + n],
                                        tf[(3 * 32 + l) * 33 + n]);
        __half2 h45 = __floats2half2_rn(tf[(4 * 32 + l) * 33 + n],
                                        tf[(5 * 32 + l) * 33 + n]);
        __half2 h67 = __floats2half2_rn(tf[(6 * 32 + l) * 33 + n],
                                        tf[(7 * 32 + l) * 33 + n]);
        uint4 val;
        val.x = *reinterpret_cast<uint32_t*>(&h01);
        val.y = *reinterpret_cast<uint32_t*>(&h23);
        val.z = *reinterpret_cast<uint32_t*>(&h45);
        val.w = *reinterpret_cast<uint32_t*>(&h67);
        *reinterpret_cast<uint4*>(
            &g_xh[((size_t)(n0 + n) * B_ + b0 + l) * C_IN_]) = val;
    }
}

// ---------------------------------------------------------------------------
// K2: tensor-core main kernel.
// Per item (n, 16-b tile): D(16b x 8d) = A(16b x 80ck) x B(80ck x 8d) via
// 5x mma.sync.m16n8k16 split into TWO independent accumulator chains
// (even q -> cE [bias-init], odd q -> cO [zero-init], merged with FADDs)
// to halve the serial HMMA RAW-latency depth. q=4 peeled: only 2 loads,
// second A-row zero (its B half is the k=9 pad).
// Gather address = base + (nbr<<12) + rowoff (32-bit; nbr pre-shifted).
// grid (N/16, B/64) = 1024 blocks, 4 CTAs/SM.
// ---------------------------------------------------------------------------
#define SIDX(d, r, nl) ((d) * 1092 + (r) * 17 + (nl))

#define MMA4(C0, C1, C2, C3, A0, A1, A2, A3, B0r, B1r)                       \
    asm volatile(                                                            \
        "mma.sync.aligned.m16n8k16.row.col.f32.f16.f16.f32 "                 \
        "{%0,%1,%2,%3}, {%4,%5,%6,%7}, {%8,%9}, {%0,%1,%2,%3};"              \
        : "+f"(C0), "+f"(C1), "+f"(C2), "+f"(C3)                             \
        : "r"(A0), "r"(A1), "r"(A2), "r"(A3), "r"(B0r), "r"(B1r))

__global__ __launch_bounds__(256, 4)
void lattice_main_kernel(const int*   __restrict__ nbr,
                         const int*   __restrict__ sub_ids,
                         const float* __restrict__ weight,
                         const float* __restrict__ bias,
                         float*       __restrict__ out)
{
    __shared__ float sw[W_ELEMS];        // 4.6 KB
    __shared__ float sout[8 * 1092];     // 34.9 KB
    __shared__ int   snbr[NT][10];       // pre-shifted nbr << 12, k padded to 10
    __shared__ int   ssub[NT];
    __shared__ float sbias[S_ * C_OUT_];

    const int tid = threadIdx.x;
    const int l   = tid & 31;
    const int w   = tid >> 5;
    const int g   = l >> 2;     // groupID (fragment row / d for B)
    const int t   = l & 3;      // thread-in-group

    const int n0 = blockIdx.x * NT;
    const int b0 = blockIdx.y * BT;

    // Prologue: weights + metadata to smem.
    #pragma unroll
    for (int i = tid; i < W_ELEMS; i += 256) sw[i] = weight[i];
    if (tid < NT * 10) {
        const int nl = tid / 10, kk = tid % 10;
        snbr[nl][kk] = nbr[(n0 + nl) * K_ + (kk < K_ ? kk : K_ - 1)] << 12;
    } else if (tid < NT * 10 + NT) {
        ssub[tid - NT * 10] = sub_ids[n0 + (tid - NT * 10)];
    } else if (tid < NT * 10 + NT + S_ * C_OUT_) {
        sbias[tid - NT * 10 - NT] = bias[tid - NT * 10 - NT];
    }
    __syncthreads();

    // Build B fragments (fp16) for both s, all 5 K-chunks.
    // bf0 = {W[s][2t][2q][g], W[s][2t+1][2q][g]}, bf1 same with k=2q+1 (q=4: zero).
    uint32_t bf0[S_][5], bf1[S_][5];
    #pragma unroll
    for (int s = 0; s < S_; ++s) {
        #pragma unroll
        for (int q = 0; q < 5; ++q) {
            const int base0 = ((s * C_IN_ + 2 * t)     * K_ + 2 * q) * C_OUT_ + g;
            const int base1 = ((s * C_IN_ + 2 * t + 1) * K_ + 2 * q) * C_OUT_ + g;
            __half2 h0 = __floats2half2_rn(sw[base0], sw[base1]);
            bf0[s][q] = *reinterpret_cast<uint32_t*>(&h0);
            if (q < 4) {
                __half2 h1 = __floats2half2_rn(sw[base0 + C_OUT_], sw[base1 + C_OUT_]);
                bf1[s][q] = *reinterpret_cast<uint32_t*>(&h1);
            } else {
                bf1[s][q] = 0u;
            }
        }
    }

    const char* xbase = reinterpret_cast<const char*>(g_xh);

    // Main: 8 items per warp. item = w*8 + it -> nl = item>>2, bt = item&3.
    #pragma unroll 1
    for (int it = 0; it < 8; ++it) {
        const int item = w * 8 + it;
        const int nl = item >> 2;
        const int bt = item & 3;
        const int s  = ssub[nl];                 // warp-uniform
        const int* nbrn = snbr[nl];

        // Chain E (q = 0, 2, 4): bias-initialized. Chain O (q = 1, 3): zero.
        float e0 = sbias[s * C_OUT_ + 2 * t];
        float e1 = sbias[s * C_OUT_ + 2 * t + 1];
        float e2 = e0, e3 = e1;
        float o0 = 0.f, o1 = 0.f, o2 = 0.f, o3 = 0.f;

        // byte offset within an n-plane: ((b0 + bt*16 + g)*8 + 2t)*2 < 4096
        const uint32_t rowoff = (uint32_t)((b0 + bt * 16 + g) * 16 + 4 * t);

        #pragma unroll
        for (int q = 0; q < 2; ++q) {   // q-pairs (0,1) and (2,3)
            const uint32_t oa = (uint32_t)nbrn[4 * q]     + rowoff;
            const uint32_t ob = (uint32_t)nbrn[4 * q + 1] + rowoff;
            const uint32_t oc = (uint32_t)nbrn[4 * q + 2] + rowoff;
            const uint32_t od = (uint32_t)nbrn[4 * q + 3] + rowoff;
            const uint32_t aE0 = __ldg(reinterpret_cast<const uint32_t*>(xbase + oa));
            const uint32_t aE1 = __ldg(reinterpret_cast<const uint32_t*>(xbase + oa + 128));
            const uint32_t aE2 = __ldg(reinterpret_cast<const uint32_t*>(xbase + ob));
            const uint32_t aE3 = __ldg(reinterpret_cast<const uint32_t*>(xbase + ob + 128));
            const uint32_t aO0 = __ldg(reinterpret_cast<const uint32_t*>(xbase + oc));
            const uint32_t aO1 = __ldg(reinterpret_cast<const uint32_t*>(xbase + oc + 128));
            const uint32_t aO2 = __ldg(reinterpret_cast<const uint32_t*>(xbase + od));
            const uint32_t aO3 = __ldg(reinterpret_cast<const uint32_t*>(xbase + od + 128));
            const int qe = 2 * q, qo = 2 * q + 1;
            const uint32_t BE0 = s ? bf0[1][qe] : bf0[0][qe];
            const uint32_t BE1 = s ? bf1[1][qe] : bf1[0][qe];
            const uint32_t BO0 = s ? bf0[1][qo] : bf0[0][qo];
            const uint32_t BO1 = s ? bf1[1][qo] : bf1[0][qo];
            MMA4(e0, e1, e2, e3, aE0, aE1, aE2, aE3, BE0, BE1);
            MMA4(o0, o1, o2, o3, aO0, aO1, aO2, aO3, BO0, BO1);
        }

        {   // q = 4 peeled: k=8 real row only; second row zero (k=9 pad).
            const uint32_t o8 = (uint32_t)nbrn[8] + rowoff;
            const uint32_t a0 = __ldg(reinterpret_cast<const uint32_t*>(xbase + o8));
            const uint32_t a1 = __ldg(reinterpret_cast<const uint32_t*>(xbase + o8 + 128));
            const uint32_t B0 = s ? bf0[1][4] : bf0[0][4];
            MMA4(e0, e1, e2, e3, a0, a1, 0u, 0u, B0, 0u);
        }

        // Merge chains and stage. Banks (4d + 17r + nl) bijective -> conflict-free.
        const int r = bt * 16 + g;
        sout[SIDX(2 * t,     r,     nl)] = e0 + o0;
        sout[SIDX(2 * t + 1, r,     nl)] = e1 + o1;
        sout[SIDX(2 * t,     r + 8, nl)] = e2 + o2;
        sout[SIDX(2 * t + 1, r + 8, nl)] = e3 + o3;
    }
    __syncthreads();

    // Epilogue: 512 (b,d) rows x 16 n. Warp w owns rows [w*64, w*64+64);
    // half-warps cover row pairs; 16 lanes = 16 consecutive n (64B line).
    {
        const int h  = l >> 4;
        const int nl = l & 15;
        #pragma unroll
        for (int p = 0; p < 32; ++p) {
            const int r512 = w * 64 + 2 * p + h;   // = b*8 + d
            const int b = r512 >> 3;
            const int d = r512 & 7;
            const float v = sout[SIDX(d, b, nl)];
            out[((size_t)(b0 + b) * C_OUT_ + d) * N_ + n0 + nl] = v;
        }
    }
}

extern "C" void kernel_launch(void* const* d_in, const int* in_sizes, int n_in,
                              void* d_out, int out_size)
{
    const float* x       = (const float*)d_in[0];   // (B, C_IN, N) f32
    const int*   nbr     = (const int*)  d_in[1];   // (N, K) i32
    const int*   sub_ids = (const int*)  d_in[2];   // (N,) i32
    const float* weight  = (const float*)d_in[3];   // (S, C_IN, K, C_OUT) f32
    const float* bias    = (const float*)d_in[4];   // (S, C_OUT) f32
    float*       out     = (float*)d_out;           // (B, C_OUT, N) f32

    dim3 tgrid(N_ / 32, B_ / 32);
    transpose_x_kernel<<<tgrid, 256>>>(x);

    dim3 mgrid(N_ / NT, B_ / BT);
    lattice_main_kernel<<<mgrid, 256>>>(nbr, sub_ids, weight, bias, out);
}

// round 16
// speedup vs baseline: 1.0605x; 1.0179x over previous
#include <cuda_runtime.h>
#include <cuda_fp16.h>
#include <cstdint>

// Problem constants
#define B_     256
#define C_IN_  8
#define N_     4096
#define K_     9
#define S_     2
#define C_OUT_ 8

#define W_ELEMS (S_ * C_IN_ * K_ * C_OUT_)   // 1152 floats

// Main tiling: block = 16 n x 64 b, 8 warps. Warp-item = (n, 16-b tile).
#define NT  16
#define BT  64

// Scratch: x as fp16 in (n, b, c) layout — c innermost (8 halves = 16B per (n,b)).
// One n-plane = B_*C_IN_*2 = 4096 bytes (power of 2 -> shift addressing).
__device__ __half g_xh[N_ * B_ * C_IN_];   // 16.8 MB

// ---------------------------------------------------------------------------
// K1: x (B, C_IN, N) f32 -> g_xh (N, B, C_IN) fp16.
// Block: 32 n x 32 b x 8 c. Phase-1 uses LDG.128 (4 lines per instr).
// grid (N/32, B/32) = 1024 blocks.
// ---------------------------------------------------------------------------
__global__ __launch_bounds__(256) void transpose_x_kernel(const float* __restrict__ x)
{
    __shared__ float tf[256 * 33];   // 33.8 KB
    const int tid = threadIdx.x;
    const int l   = tid & 31;
    const int w   = tid >> 5;
    const int n0  = blockIdx.x * 32;
    const int b0  = blockIdx.y * 32;

    // Phase 1: warp w covers rows w*32 + 4i + (l>>3); lanes 0..7 = one row's
    // 32 n as 8 consecutive float4 (one 128B line per 8 lanes).
    // STS banks: ((l>>3) + 4*(l&7) + k) mod 32 distinct per k -> conflict-free.
    #pragma unroll
    for (int i = 0; i < 8; ++i) {
        const int row = w * 32 + i * 4 + (l >> 3);   // (b,c) index
        const int b = row >> 3;
        const int c = row & 7;
        const int nn = (l & 7) * 4;
        const float4 v = *reinterpret_cast<const float4*>(
            &x[((size_t)(b0 + b) * C_IN_ + c) * N_ + n0 + nn]);
        float* dst = &tf[(c * 32 + b) * 33 + nn];
        dst[0] = v.x; dst[1] = v.y; dst[2] = v.z; dst[3] = v.w;
    }
    __syncthreads();

    // Phase 2: per iteration warp w handles n = w + 8i, lanes = b.
    // Banks (33*(32c+b) + n) mod 32 = (b + n) mod 32: lanes=b -> conflict-free.
    #pragma unroll
    for (int i = 0; i < 4; ++i) {
        const int n = w + 8 * i;
        __half2 h01 = __floats2half2_rn(tf[(0 * 32 + l) * 33 + n],
                                        tf[(1 * 32 + l) * 33 + n]);
        __half2 h23 = __floats2half2_rn(tf[(2 * 32 + l) * 33 + n],
                                        tf[(3 * 32 + l) * 33 + n]);
        __half2 h45 = __floats2half2_rn(tf[(4 * 32 + l) * 33 + n],
                                        tf[(5 * 32 + l) * 33 + n]);
        __half2 h67 = __floats2half2_rn(tf[(6 * 32 + l) * 33 + n],
                                        tf[(7 * 32 + l) * 33 + n]);
        uint4 val;
        val.x = *reinterpret_cast<uint32_t*>(&h01);
        val.y = *reinterpret_cast<uint32_t*>(&h23);
        val.z = *reinterpret_cast<uint32_t*>(&h45);
        val.w = *reinterpret_cast<uint32_t*>(&h67);
        *reinterpret_cast<uint4*>(
            &g_xh[((size_t)(n0 + n) * B_ + b0 + l) * C_IN_]) = val;
    }
}

// ---------------------------------------------------------------------------
// K2: tensor-core main kernel, ITEM-PAIR pipelined.
// Items 2j and 2j+1 of a warp share n (same s, same neighbors) and differ
// only in the 16-b sub-tile -> a pair shares B fragments and issues 16
// gather loads per q-pair (2x MLP), feeding 4 independent MMA chains.
// B fragments live in smem (uint2 per lane per (s,q)) to free ~20 regs.
// Gather address = base + (nbr<<12) + rowoff (32-bit; nbr pre-shifted).
// grid (N/16, B/64) = 1024 blocks, 4 CTAs/SM.
// ---------------------------------------------------------------------------
#define SIDX(d, r, nl) ((d) * 1092 + (r) * 17 + (nl))

#define MMA4(C0, C1, C2, C3, A0, A1, A2, A3, B0r, B1r)                       \
    asm volatile(                                                            \
        "mma.sync.aligned.m16n8k16.row.col.f32.f16.f16.f32 "                 \
        "{%0,%1,%2,%3}, {%4,%5,%6,%7}, {%8,%9}, {%0,%1,%2,%3};"              \
        : "+f"(C0), "+f"(C1), "+f"(C2), "+f"(C3)                             \
        : "r"(A0), "r"(A1), "r"(A2), "r"(A3), "r"(B0r), "r"(B1r))

#define LDGU(off) __ldg(reinterpret_cast<const uint32_t*>(xbase + (off)))

__global__ __launch_bounds__(256, 4)
void lattice_main_kernel(const int*   __restrict__ nbr,
                         const int*   __restrict__ sub_ids,
                         const float* __restrict__ weight,
                         const float* __restrict__ bias,
                         float*       __restrict__ out)
{
    __shared__ float sw[W_ELEMS];        // 4.6 KB
    __shared__ float sout[8 * 1092];     // 34.9 KB
    __shared__ int   snbr[NT][9];        // pre-shifted nbr << 12
    __shared__ int   ssub[NT];
    __shared__ float sbias[S_ * C_OUT_];
    __shared__ uint2 sbf[S_ * 5 * 32];   // B fragments per (s, q, lane): 2.5 KB

    const int tid = threadIdx.x;
    const int l   = tid & 31;
    const int w   = tid >> 5;
    const int g   = l >> 2;     // groupID (fragment row / d for B)
    const int t   = l & 3;      // thread-in-group

    const int n0 = blockIdx.x * NT;
    const int b0 = blockIdx.y * BT;

    // Prologue: weights + metadata to smem.
    #pragma unroll
    for (int i = tid; i < W_ELEMS; i += 256) sw[i] = weight[i];
    if (tid < NT * 9) {
        const int nl = tid / 9, kk = tid % 9;
        snbr[nl][kk] = nbr[(n0 + nl) * K_ + kk] << 12;   // byte offset of n-plane
    } else if (tid < NT * 9 + NT) {
        ssub[tid - NT * 9] = sub_ids[n0 + (tid - NT * 9)];
    } else if (tid < NT * 9 + NT + S_ * C_OUT_) {
        sbias[tid - NT * 9 - NT] = bias[tid - NT * 9 - NT];
    }
    __syncthreads();

    // Build B fragments in smem: warp s (=0,1) builds its own s.
    // bf.x = {W[s][2t][2q][g], W[s][2t+1][2q][g]} fp16x2; bf.y = k=2q+1 (q=4: 0).
    if (w < S_) {
        const int s = w;
        #pragma unroll
        for (int q = 0; q < 5; ++q) {
            const int base0 = ((s * C_IN_ + 2 * t)     * K_ + 2 * q) * C_OUT_ + g;
            const int base1 = ((s * C_IN_ + 2 * t + 1) * K_ + 2 * q) * C_OUT_ + g;
            __half2 h0 = __floats2half2_rn(sw[base0], sw[base1]);
            uint32_t v0 = *reinterpret_cast<uint32_t*>(&h0);
            uint32_t v1 = 0u;
            if (q < 4) {
                __half2 h1 = __floats2half2_rn(sw[base0 + C_OUT_], sw[base1 + C_OUT_]);
                v1 = *reinterpret_cast<uint32_t*>(&h1);
            }
            sbf[(s * 5 + q) * 32 + l] = make_uint2(v0, v1);
        }
    }
    __syncthreads();

    const char* xbase = reinterpret_cast<const char*>(g_xh);
    // byte offset of (b0 + g, c=2t) within an n-plane
    const uint32_t rowbase = (uint32_t)((b0 + g) * 16 + 4 * t);

    // Main: 4 pair-iterations; pair jp = items (w*8+2jp, w*8+2jp+1).
    // Both items share nl = 2w + (jp>>1); bt0 = (jp&1)*2, bt1 = bt0+1.
    #pragma unroll 1
    for (int jp = 0; jp < 4; ++jp) {
        const int nl = 2 * w + (jp >> 1);
        const int s  = ssub[nl];                 // warp-uniform
        const int* nbrn = snbr[nl];
        const uint2* sbf_s = sbf + s * 5 * 32 + l;

        const uint32_t rA = rowbase + (uint32_t)((jp & 1) * 512);  // bt0*256
        const uint32_t rB = rA + 256;                              // bt1*256

        const float bi0 = sbias[s * C_OUT_ + 2 * t];
        const float bi1 = sbias[s * C_OUT_ + 2 * t + 1];
        float eA0 = bi0, eA1 = bi1, eA2 = bi0, eA3 = bi1;
        float oA0 = 0.f, oA1 = 0.f, oA2 = 0.f, oA3 = 0.f;
        float eB0 = bi0, eB1 = bi1, eB2 = bi0, eB3 = bi1;
        float oB0 = 0.f, oB1 = 0.f, oB2 = 0.f, oB3 = 0.f;

        #pragma unroll
        for (int qp = 0; qp < 2; ++qp) {   // q-pairs (0,1) and (2,3)
            const uint32_t na = (uint32_t)nbrn[4 * qp];
            const uint32_t nb = (uint32_t)nbrn[4 * qp + 1];
            const uint32_t nc = (uint32_t)nbrn[4 * qp + 2];
            const uint32_t nd = (uint32_t)nbrn[4 * qp + 3];
            // item A (bt0): 8 loads
            const uint32_t aE0 = LDGU(na + rA), aE1 = LDGU(na + rA + 128);
            const uint32_t aE2 = LDGU(nb + rA), aE3 = LDGU(nb + rA + 128);
            const uint32_t aO0 = LDGU(nc + rA), aO1 = LDGU(nc + rA + 128);
            const uint32_t aO2 = LDGU(nd + rA), aO3 = LDGU(nd + rA + 128);
            // item B (bt1): 8 loads
            const uint32_t bE0 = LDGU(na + rB), bE1 = LDGU(na + rB + 128);
            const uint32_t bE2 = LDGU(nb + rB), bE3 = LDGU(nb + rB + 128);
            const uint32_t bO0 = LDGU(nc + rB), bO1 = LDGU(nc + rB + 128);
            const uint32_t bO2 = LDGU(nd + rB), bO3 = LDGU(nd + rB + 128);
            // shared B fragments (lane-indexed LDS.64, conflict-free)
            const uint2 BE = sbf_s[(2 * qp) * 32];
            const uint2 BO = sbf_s[(2 * qp + 1) * 32];
            // 4 independent MMA chains
            MMA4(eA0, eA1, eA2, eA3, aE0, aE1, aE2, aE3, BE.x, BE.y);
            MMA4(oA0, oA1, oA2, oA3, aO0, aO1, aO2, aO3, BO.x, BO.y);
            MMA4(eB0, eB1, eB2, eB3, bE0, bE1, bE2, bE3, BE.x, BE.y);
            MMA4(oB0, oB1, oB2, oB3, bO0, bO1, bO2, bO3, BO.x, BO.y);
        }

        {   // q = 4 peeled: k=8 real row only; second row zero (k=9 pad).
            const uint32_t n8 = (uint32_t)nbrn[8];
            const uint32_t a0 = LDGU(n8 + rA), a1 = LDGU(n8 + rA + 128);
            const uint32_t b0v = LDGU(n8 + rB), b1v = LDGU(n8 + rB + 128);
            const uint2 B4 = sbf_s[4 * 32];
            MMA4(eA0, eA1, eA2, eA3, a0, a1, 0u, 0u, B4.x, 0u);
            MMA4(eB0, eB1, eB2, eB3, b0v, b1v, 0u, 0u, B4.x, 0u);
        }

        // Merge chains, stage both items. Banks (4d + 17r + nl) bijective.
        const int rr0 = (jp & 1) * 32 + g;        // item A rows rr0, rr0+8
        const int rr1 = rr0 + 16;                 // item B rows rr1, rr1+8
        sout[SIDX(2 * t,     rr0,      nl)] = eA0 + oA0;
        sout[SIDX(2 * t + 1, rr0,      nl)] = eA1 + oA1;
        sout[SIDX(2 * t,     rr0 + 8,  nl)] = eA2 + oA2;
        sout[SIDX(2 * t + 1, rr0 + 8,  nl)] = eA3 + oA3;
        sout[SIDX(2 * t,     rr1,      nl)] = eB0 + oB0;
        sout[SIDX(2 * t + 1, rr1,      nl)] = eB1 + oB1;
        sout[SIDX(2 * t,     rr1 + 8,  nl)] = eB2 + oB2;
        sout[SIDX(2 * t + 1, rr1 + 8,  nl)] = eB3 + oB3;
    }
    __syncthreads();

    // Epilogue: 512 (b,d) rows x 16 n. Warp w owns rows [w*64, w*64+64);
    // half-warps cover row pairs; 16 lanes = 16 consecutive n (64B line).
    {
        const int h  = l >> 4;
        const int nl = l & 15;
        #pragma unroll
        for (int p = 0; p < 32; ++p) {
            const int r512 = w * 64 + 2 * p + h;   // = b*8 + d
            const int b = r512 >> 3;
            const int d = r512 & 7;
            const float v = sout[SIDX(d, b, nl)];
            out[((size_t)(b0 + b) * C_OUT_ + d) * N_ + n0 + nl] = v;
        }
    }
}

extern "C" void kernel_launch(void* const* d_in, const int* in_sizes, int n_in,
                              void* d_out, int out_size)
{
    const float* x       = (const float*)d_in[0];   // (B, C_IN, N) f32
    const int*   nbr     = (const int*)  d_in[1];   // (N, K) i32
    const int*   sub_ids = (const int*)  d_in[2];   // (N,) i32
    const float* weight  = (const float*)d_in[3];   // (S, C_IN, K, C_OUT) f32
    const float* bias    = (const float*)d_in[4];   // (S, C_OUT) f32
    float*       out     = (float*)d_out;           // (B, C_OUT, N) f32

    dim3 tgrid(N_ / 32, B_ / 32);
    transpose_x_kernel<<<tgrid, 256>>>(x);

    dim3 mgrid(N_ / NT, B_ / BT);
    lattice_main_kernel<<<mgrid, 256>>>(nbr, sub_ids, weight, bias, out);
}

// round 17
// speedup vs baseline: 1.0864x; 1.0244x over previous
#include <cuda_runtime.h>
#include <cuda_fp16.h>
#include <cstdint>

// Problem constants
#define B_     256
#define C_IN_  8
#define N_     4096
#define K_     9
#define S_     2
#define C_OUT_ 8

#define W_ELEMS (S_ * C_IN_ * K_ * C_OUT_)   // 1152 floats

// Main tiling: block = 16 n x 64 b, 8 warps. Warp-item = (n, 16-b tile).
#define NT  16
#define BT  64

// Scratch: x as fp16 in (n, b, c) layout — c innermost (8 halves = 16B per (n,b)).
// One n-plane = B_*C_IN_*2 = 4096 bytes (power of 2 -> shift addressing).
__device__ __half g_xh[N_ * B_ * C_IN_];   // 16.8 MB

// ---------------------------------------------------------------------------
// K1: x (B, C_IN, N) f32 -> g_xh (N, B, C_IN) fp16.
// Block: 32 n x 32 b x 8 c. Phase-1 uses LDG.128. grid (N/32, B/32).
// ---------------------------------------------------------------------------
__global__ __launch_bounds__(256) void transpose_x_kernel(const float* __restrict__ x)
{
    __shared__ float tf[256 * 33];   // 33.8 KB
    const int tid = threadIdx.x;
    const int l   = tid & 31;
    const int w   = tid >> 5;
    const int n0  = blockIdx.x * 32;
    const int b0  = blockIdx.y * 32;

    // Phase 1: warp w covers rows w*32 + 4i + (l>>3); lanes 0..7 = one row's
    // 32 n as 8 consecutive float4. STS banks conflict-free.
    #pragma unroll
    for (int i = 0; i < 8; ++i) {
        const int row = w * 32 + i * 4 + (l >> 3);   // (b,c) index
        const int b = row >> 3;
        const int c = row & 7;
        const int nn = (l & 7) * 4;
        const float4 v = *reinterpret_cast<const float4*>(
            &x[((size_t)(b0 + b) * C_IN_ + c) * N_ + n0 + nn]);
        float* dst = &tf[(c * 32 + b) * 33 + nn];
        dst[0] = v.x; dst[1] = v.y; dst[2] = v.z; dst[3] = v.w;
    }
    __syncthreads();

    // Phase 2: per iteration warp w handles n = w + 8i, lanes = b.
    // Banks (b + n) mod 32: lanes=b -> conflict-free.
    #pragma unroll
    for (int i = 0; i < 4; ++i) {
        const int n = w + 8 * i;
        __half2 h01 = __floats2half2_rn(tf[(0 * 32 + l) * 33 + n],
                                        tf[(1 * 32 + l) * 33 + n]);
        __half2 h23 = __floats2half2_rn(tf[(2 * 32 + l) * 33 + n],
                                        tf[(3 * 32 + l) * 33 + n]);
        __half2 h45 = __floats2half2_rn(tf[(4 * 32 + l) * 33 + n],
                                        tf[(5 * 32 + l) * 33 + n]);
        __half2 h67 = __floats2half2_rn(tf[(6 * 32 + l) * 33 + n],
                                        tf[(7 * 32 + l) * 33 + n]);
        uint4 val;
        val.x = *reinterpret_cast<uint32_t*>(&h01);
        val.y = *reinterpret_cast<uint32_t*>(&h23);
        val.z = *reinterpret_cast<uint32_t*>(&h45);
        val.w = *reinterpret_cast<uint32_t*>(&h67);
        *reinterpret_cast<uint4*>(
            &g_xh[((size_t)(n0 + n) * B_ + b0 + l) * C_IN_]) = val;
    }
}

// ---------------------------------------------------------------------------
// K2: tensor-core main kernel, item-pair pipelined (R16 body) with
//   (a) #pragma unroll 2 on the pair loop (cross-pair load/MMA overlap),
//   (b) linearized epilogue (immediate-stride walking pointers).
// grid (N/16, B/64) = 1024 blocks, 4 CTAs/SM.
// ---------------------------------------------------------------------------
#define SIDX(d, r, nl) ((d) * 1092 + (r) * 17 + (nl))

#define MMA4(C0, C1, C2, C3, A0, A1, A2, A3, B0r, B1r)                       \
    asm volatile(                                                            \
        "mma.sync.aligned.m16n8k16.row.col.f32.f16.f16.f32 "                 \
        "{%0,%1,%2,%3}, {%4,%5,%6,%7}, {%8,%9}, {%0,%1,%2,%3};"              \
        : "+f"(C0), "+f"(C1), "+f"(C2), "+f"(C3)                             \
        : "r"(A0), "r"(A1), "r"(A2), "r"(A3), "r"(B0r), "r"(B1r))

#define LDGU(off) __ldg(reinterpret_cast<const uint32_t*>(xbase + (off)))

__global__ __launch_bounds__(256, 4)
void lattice_main_kernel(const int*   __restrict__ nbr,
                         const int*   __restrict__ sub_ids,
                         const float* __restrict__ weight,
                         const float* __restrict__ bias,
                         float*       __restrict__ out)
{
    __shared__ float sw[W_ELEMS];        // 4.6 KB
    __shared__ float sout[8 * 1092];     // 34.9 KB
    __shared__ int   snbr[NT][9];        // pre-shifted nbr << 12
    __shared__ int   ssub[NT];
    __shared__ float sbias[S_ * C_OUT_];
    __shared__ uint2 sbf[S_ * 5 * 32];   // B fragments per (s, q, lane): 2.5 KB

    const int tid = threadIdx.x;
    const int l   = tid & 31;
    const int w   = tid >> 5;
    const int g   = l >> 2;     // groupID (fragment row / d for B)
    const int t   = l & 3;      // thread-in-group

    const int n0 = blockIdx.x * NT;
    const int b0 = blockIdx.y * BT;

    // Prologue: weights + metadata to smem.
    #pragma unroll
    for (int i = tid; i < W_ELEMS; i += 256) sw[i] = weight[i];
    if (tid < NT * 9) {
        const int nl = tid / 9, kk = tid % 9;
        snbr[nl][kk] = nbr[(n0 + nl) * K_ + kk] << 12;   // byte offset of n-plane
    } else if (tid < NT * 9 + NT) {
        ssub[tid - NT * 9] = sub_ids[n0 + (tid - NT * 9)];
    } else if (tid < NT * 9 + NT + S_ * C_OUT_) {
        sbias[tid - NT * 9 - NT] = bias[tid - NT * 9 - NT];
    }
    __syncthreads();

    // Build B fragments in smem: warp s (=0,1) builds its own s.
    if (w < S_) {
        const int s = w;
        #pragma unroll
        for (int q = 0; q < 5; ++q) {
            const int base0 = ((s * C_IN_ + 2 * t)     * K_ + 2 * q) * C_OUT_ + g;
            const int base1 = ((s * C_IN_ + 2 * t + 1) * K_ + 2 * q) * C_OUT_ + g;
            __half2 h0 = __floats2half2_rn(sw[base0], sw[base1]);
            uint32_t v0 = *reinterpret_cast<uint32_t*>(&h0);
            uint32_t v1 = 0u;
            if (q < 4) {
                __half2 h1 = __floats2half2_rn(sw[base0 + C_OUT_], sw[base1 + C_OUT_]);
                v1 = *reinterpret_cast<uint32_t*>(&h1);
            }
            sbf[(s * 5 + q) * 32 + l] = make_uint2(v0, v1);
        }
    }
    __syncthreads();

    const char* xbase = reinterpret_cast<const char*>(g_xh);
    // byte offset of (b0 + g, c=2t) within an n-plane
    const uint32_t rowbase = (uint32_t)((b0 + g) * 16 + 4 * t);

    // Main: 4 pair-iterations; pair jp = items (w*8+2jp, w*8+2jp+1).
    // Both items share nl = 2w + (jp>>1); bt0 = (jp&1)*2, bt1 = bt0+1.
    #pragma unroll 2
    for (int jp = 0; jp < 4; ++jp) {
        const int nl = 2 * w + (jp >> 1);
        const int s  = ssub[nl];                 // warp-uniform
        const int* nbrn = snbr[nl];
        const uint2* sbf_s = sbf + s * 5 * 32 + l;

        const uint32_t rA = rowbase + (uint32_t)((jp & 1) * 512);  // bt0*256
        const uint32_t rB = rA + 256;                              // bt1*256

        const float bi0 = sbias[s * C_OUT_ + 2 * t];
        const float bi1 = sbias[s * C_OUT_ + 2 * t + 1];
        float eA0 = bi0, eA1 = bi1, eA2 = bi0, eA3 = bi1;
        float oA0 = 0.f, oA1 = 0.f, oA2 = 0.f, oA3 = 0.f;
        float eB0 = bi0, eB1 = bi1, eB2 = bi0, eB3 = bi1;
        float oB0 = 0.f, oB1 = 0.f, oB2 = 0.f, oB3 = 0.f;

        #pragma unroll
        for (int qp = 0; qp < 2; ++qp) {   // q-pairs (0,1) and (2,3)
            const uint32_t na = (uint32_t)nbrn[4 * qp]     + rA;
            const uint32_t nb = (uint32_t)nbrn[4 * qp + 1] + rA;
            const uint32_t nc = (uint32_t)nbrn[4 * qp + 2] + rA;
            const uint32_t nd = (uint32_t)nbrn[4 * qp + 3] + rA;
            // item A (bt0) at +0/+128, item B (bt1) at +256/+384 (immediates)
            const uint32_t aE0 = LDGU(na),       aE1 = LDGU(na + 128);
            const uint32_t aE2 = LDGU(nb),       aE3 = LDGU(nb + 128);
            const uint32_t aO0 = LDGU(nc),       aO1 = LDGU(nc + 128);
            const uint32_t aO2 = LDGU(nd),       aO3 = LDGU(nd + 128);
            const uint32_t bE0 = LDGU(na + 256), bE1 = LDGU(na + 384);
            const uint32_t bE2 = LDGU(nb + 256), bE3 = LDGU(nb + 384);
            const uint32_t bO0 = LDGU(nc + 256), bO1 = LDGU(nc + 384);
            const uint32_t bO2 = LDGU(nd + 256), bO3 = LDGU(nd + 384);
            // shared B fragments (lane-indexed LDS.64, conflict-free per phase)
            const uint2 BE = sbf_s[(2 * qp) * 32];
            const uint2 BO = sbf_s[(2 * qp + 1) * 32];
            // 4 independent MMA chains
            MMA4(eA0, eA1, eA2, eA3, aE0, aE1, aE2, aE3, BE.x, BE.y);
            MMA4(oA0, oA1, oA2, oA3, aO0, aO1, aO2, aO3, BO.x, BO.y);
            MMA4(eB0, eB1, eB2, eB3, bE0, bE1, bE2, bE3, BE.x, BE.y);
            MMA4(oB0, oB1, oB2, oB3, bO0, bO1, bO2, bO3, BO.x, BO.y);
        }

        {   // q = 4 peeled: k=8 real row only; second row zero (k=9 pad).
            const uint32_t n8 = (uint32_t)nbrn[8] + rA;
            const uint32_t a0 = LDGU(n8),       a1 = LDGU(n8 + 128);
            const uint32_t b0v = LDGU(n8 + 256), b1v = LDGU(n8 + 384);
            const uint2 B4 = sbf_s[4 * 32];
            MMA4(eA0, eA1, eA2, eA3, a0, a1, 0u, 0u, B4.x, 0u);
            MMA4(eB0, eB1, eB2, eB3, b0v, b1v, 0u, 0u, B4.x, 0u);
        }

        // Merge chains, stage both items. Banks (4d + 17r + nl) bijective.
        const int rr0 = (jp & 1) * 32 + g;        // item A rows rr0, rr0+8
        const int rr1 = rr0 + 16;                 // item B rows rr1, rr1+8
        sout[SIDX(2 * t,     rr0,      nl)] = eA0 + oA0;
        sout[SIDX(2 * t + 1, rr0,      nl)] = eA1 + oA1;
        sout[SIDX(2 * t,     rr0 + 8,  nl)] = eA2 + oA2;
        sout[SIDX(2 * t + 1, rr0 + 8,  nl)] = eA3 + oA3;
        sout[SIDX(2 * t,     rr1,      nl)] = eB0 + oB0;
        sout[SIDX(2 * t + 1, rr1,      nl)] = eB1 + oB1;
        sout[SIDX(2 * t,     rr1 + 8,  nl)] = eB2 + oB2;
        sout[SIDX(2 * t + 1, rr1 + 8,  nl)] = eB3 + oB3;
    }
    __syncthreads();

    // Epilogue (linearized): warp w owns b-local rows w*8 .. w*8+7, all 8 d.
    // Half-warp h covers b-parity h; lanes = 16 consecutive n (64B line).
    // All inner strides are immediates off two walking pointers.
    {
        const int h  = l >> 4;
        const int nl = l & 15;
        const float* sbase = sout + (w * 8 + h) * 17 + nl;
        float* gbase = out + ((size_t)(b0 + w * 8 + h) * C_OUT_) * N_ + n0 + nl;
        #pragma unroll
        for (int pb = 0; pb < 4; ++pb) {
            #pragma unroll
            for (int dd = 0; dd < 8; ++dd) {
                gbase[dd * N_] = sbase[dd * 1092];
            }
            sbase += 34;              // b-local += 2
            gbase += 16 * N_;         // b += 2  ->  +2*C_OUT_*N_
        }
    }
}

extern "C" void kernel_launch(void* const* d_in, const int* in_sizes, int n_in,
                              void* d_out, int out_size)
{
    const float* x       = (const float*)d_in[0];   // (B, C_IN, N) f32
    const int*   nbr     = (const int*)  d_in[1];   // (N, K) i32
    const int*   sub_ids = (const int*)  d_in[2];   // (N,) i32
    const float* weight  = (const float*)d_in[3];   // (S, C_IN, K, C_OUT) f32
    const float* bias    = (const float*)d_in[4];   // (S, C_OUT) f32
    float*       out     = (float*)d_out;           // (B, C_OUT, N) f32

    dim3 tgrid(N_ / 32, B_ / 32);
    transpose_x_kernel<<<tgrid, 256>>>(x);

    dim3 mgrid(N_ / NT, B_ / BT);
    lattice_main_kernel<<<mgrid, 256>>>(nbr, sub_ids, weight, bias, out);
}